// round 13
// baseline (speedup 1.0000x reference)
#include <cuda_runtime.h>

#define NR    8192
#define NQ    4096
#define KNN_K 16
#define C4    64            // 256 channels / 4 (float4)

#define NWARP        16
#define THREADS      (NWARP * 32)     // 512
#define QPB          32               // queries per block (one per lane)
#define KNN_BLOCKS   (NQ / QPB)       // 128
#define REFS_PER_WARP (NR / NWARP)    // 512
#define SAMP_PER_GRP  64              // 32 groups x 64 = 2048 samples
#define BUF_CAP      256
#define SLACK        1e-3f            // >> t<->d rounding gap (~1e-5)

typedef unsigned long long ull;

__device__ int g_knn_idx[NQ * KNN_K];

// q2/r2: jnp.sum(x*x) = sequential add of rn squares (no FMA).
__device__ __forceinline__ float sq3(float x, float y, float z) {
    return __fadd_rn(__fadd_rn(__fmul_rn(x, x), __fmul_rn(y, y)), __fmul_rn(z, z));
}
// cross: XLA dot accumulation = fmuladd chain (seed = rn product).
__device__ __forceinline__ float dot3_fma(float ax, float ay, float az,
                                          float bx, float by, float bz) {
    return __fmaf_rn(az, bz, __fmaf_rn(ay, by, __fmul_rn(ax, bx)));
}
// Lexicographic (dist, idx) as one sortable u64 (survivor buffer only).
__device__ __forceinline__ ull make_key(float d, int r) {
    unsigned b = __float_as_uint(d);
    b ^= ((unsigned)((int)b >> 31)) | 0x80000000u;
    return ((ull)b << 32) | (unsigned)r;
}

// Float-only bitonic sort of 32 lane values; returns 16th smallest (all lanes).
__device__ __forceinline__ float warp_16th(float sd, int lane) {
#pragma unroll
    for (int kk = 2; kk <= 32; kk <<= 1) {
#pragma unroll
        for (int j = kk >> 1; j > 0; j >>= 1) {
            const float o = __shfl_xor_sync(0xffffffffu, sd, j);
            const bool keepMin = (((lane & j) == 0) == ((lane & kk) == 0));
            sd = keepMin ? fminf(sd, o) : fmaxf(sd, o);
        }
    }
    return __shfl_sync(0xffffffffu, sd, KNN_K - 1);
}

// Extract 16 smallest keys from wbuf[0..cnt) into g_knn_idx for query q.
__device__ __forceinline__ void select16(ull* wbuf, int cnt, int q, int lane) {
    for (int sel = 0; sel < KNN_K; ++sel) {
        ull best = ~0ull;
        int bpos = -1;
        for (int i = lane; i < cnt; i += 32) {
            const ull v = wbuf[i];
            if (v < best) { best = v; bpos = i; }
        }
#pragma unroll
        for (int off = 16; off > 0; off >>= 1) {
            const ull ob = __shfl_down_sync(0xffffffffu, best, off);
            const int op = __shfl_down_sync(0xffffffffu, bpos, off);
            if (ob < best) { best = ob; bpos = op; }
        }
        bpos = __shfl_sync(0xffffffffu, bpos, 0);
        if (lane == 0) g_knn_idx[q * KNN_K + sel] = (int)(wbuf[bpos] & 0xffffffffu);
        if (lane == (bpos & 31)) wbuf[bpos] = ~0ull;
        __syncwarp();
    }
}

// Query-per-lane: block owns 32 queries (q = blockIdx*32 + lane). Every ref
// read is a broadcast LDS (N=1) shared by all 32 queries -> LDS traffic /32.
// Warp w scans refs [512w, 512w+512). Two-pass threshold selection.
__global__ void __launch_bounds__(THREADS, 1) knn_kernel(
        const float* __restrict__ xyz_prev,
        const float* __restrict__ xyz_cur) {
    extern __shared__ unsigned char smraw[];
    float4* sref = (float4*)smraw;                                  // 128 KB
    ull*    sbuf = (ull*)(smraw + NR * sizeof(float4));             // 32*256*8 = 64 KB
    float*  smin = (float*)(smraw + NR * sizeof(float4) + QPB * BUF_CAP * sizeof(ull));
    float*  stau = smin + 32 * 33;                                  // [32]
    int*    scnt = (int*)(stau + 32);                               // [32]

    const int tid  = threadIdx.x;
    const int warp = tid >> 5;
    const int lane = tid & 31;

    // stage refs (original order; r2 computed in-fill)
    for (int i = tid; i < NR; i += THREADS) {
        const float x = xyz_prev[3 * i + 0];
        const float y = xyz_prev[3 * i + 1];
        const float z = xyz_prev[3 * i + 2];
        sref[i] = make_float4(x, y, z, sq3(x, y, z));
    }
    if (tid < QPB) scnt[tid] = 0;
    __syncthreads();

    const int q = blockIdx.x * QPB + lane;          // this lane's query
    const float qx = xyz_cur[3 * q + 0];
    const float qy = xyz_cur[3 * q + 1];
    const float qz = xyz_cur[3 * q + 2];
    const float q2 = sq3(qx, qy, qz);

    // ---- Phase 1: two disjoint 64-sample group minima per (query, warp) ----
    // samples = every 4th ref; warp w owns sample slots [128w, 128w+128)
    const float INF = __int_as_float(0x7f800000);
    float mn0 = INF, mn1 = INF;
#pragma unroll 4
    for (int jj = 0; jj < SAMP_PER_GRP; ++jj) {
        const float4 p = sref[4 * (128 * warp + jj)];
        const float t = __fmaf_rn(-2.0f, dot3_fma(qx, qy, qz, p.x, p.y, p.z), p.w);
        mn0 = fminf(mn0, t);
    }
#pragma unroll 4
    for (int jj = SAMP_PER_GRP; jj < 2 * SAMP_PER_GRP; ++jj) {
        const float4 p = sref[4 * (128 * warp + jj)];
        const float t = __fmaf_rn(-2.0f, dot3_fma(qx, qy, qz, p.x, p.y, p.z), p.w);
        mn1 = fminf(mn1, t);
    }
    smin[(2 * warp) * 33 + lane]     = mn0;
    smin[(2 * warp + 1) * 33 + lane] = mn1;
    __syncthreads();

    // tau for block-queries j = 2w, 2w+1: 16th smallest of 32 group minima
#pragma unroll
    for (int k = 0; k < 2; ++k) {
        const int j = 2 * warp + k;
        const float v = smin[lane * 33 + j];        // conflict-free: bank (lane+j)%32
        const float tau = warp_16th(v, lane);
        if (lane == 0) stau[j] = tau;
    }
    __syncthreads();
    const float tauq = stau[lane] + SLACK;

    // ---- Phase 2: warp scans its 512-ref slice for all 32 lane-queries ----
    const int r0 = warp * REFS_PER_WARP;
    for (int rr = 0; rr < REFS_PER_WARP; rr += 4) {
        const float4 p0 = sref[r0 + rr + 0];
        const float4 p1 = sref[r0 + rr + 1];
        const float4 p2 = sref[r0 + rr + 2];
        const float4 p3 = sref[r0 + rr + 3];
        const float c0 = dot3_fma(qx, qy, qz, p0.x, p0.y, p0.z);
        const float c1 = dot3_fma(qx, qy, qz, p1.x, p1.y, p1.z);
        const float c2 = dot3_fma(qx, qy, qz, p2.x, p2.y, p2.z);
        const float c3 = dot3_fma(qx, qy, qz, p3.x, p3.y, p3.z);
        const float t0 = __fmaf_rn(-2.0f, c0, p0.w);
        const float t1 = __fmaf_rn(-2.0f, c1, p1.w);
        const float t2 = __fmaf_rn(-2.0f, c2, p2.w);
        const float t3 = __fmaf_rn(-2.0f, c3, p3.w);

#pragma unroll
        for (int j = 0; j < 4; ++j) {
            const float t  = (j == 0) ? t0 : (j == 1) ? t1 : (j == 2) ? t2 : t3;
            const float cr = (j == 0) ? c0 : (j == 1) ? c1 : (j == 2) ? c2 : c3;
            const float pw = (j == 0) ? p0.w : (j == 1) ? p1.w : (j == 2) ? p2.w : p3.w;
            if (t <= tauq) {
                // exact reference-rounded distance, rare path only
                const float d = __fmaf_rn(-2.0f, cr, __fadd_rn(q2, pw));
                const int pos = atomicAdd(&scnt[lane], 1);
                if (pos < BUF_CAP) sbuf[lane * BUF_CAP + pos] = make_key(d, r0 + rr + j);
            }
        }
    }
    __syncthreads();

    // ---- Phase 3: warp w selects for block-queries 2w, 2w+1 ----
#pragma unroll
    for (int k = 0; k < 2; ++k) {
        const int j = 2 * warp + k;
        const int cnt = min(scnt[j], BUF_CAP);      // >= 16 guaranteed
        select16(sbuf + j * BUF_CAP, cnt, blockIdx.x * QPB + j, lane);
    }
}

// One block per query. blockDim = (64, 4). Thread y owns neighbors 4y..4y+3:
// one int4 idx load -> 4 independent gathers (MLP=4), cur reused from regs.
__global__ void __launch_bounds__(256) gather_kernel(
        const float4* __restrict__ feat_prev,
        const float4* __restrict__ feat_cur,
        float4* __restrict__ out) {
    const int q  = blockIdx.x;
    const int c4 = threadIdx.x;   // 0..63
    const int y  = threadIdx.y;   // 0..3

    const float4 cur = feat_cur[q * C4 + c4];
    const int4 iv = __ldg((const int4*)(g_knn_idx + q * KNN_K + 4 * y));

    const float4 p0 = feat_prev[iv.x * C4 + c4];
    const float4 p1 = feat_prev[iv.y * C4 + c4];
    const float4 p2 = feat_prev[iv.z * C4 + c4];
    const float4 p3 = feat_prev[iv.w * C4 + c4];

    const int row0 = q * KNN_K + 4 * y;
#pragma unroll
    for (int jj = 0; jj < 4; ++jj) {
        const float4 p = (jj == 0) ? p0 : (jj == 1) ? p1 : (jj == 2) ? p2 : p3;
        float4 dv;
        dv.x = p.x - cur.x; dv.y = p.y - cur.y;
        dv.z = p.z - cur.z; dv.w = p.w - cur.w;
        const long long row = row0 + jj;
        __stcs(&out[row * 128 + c4], dv);
        __stcs(&out[row * 128 + C4 + c4], cur);
    }
}

extern "C" void kernel_launch(void* const* d_in, const int* in_sizes, int n_in,
                              void* d_out, int out_size) {
    const float*  xyz_prev  = (const float*)d_in[0];
    const float*  xyz_cur   = (const float*)d_in[1];
    const float4* feat_prev = (const float4*)d_in[2];
    const float4* feat_cur  = (const float4*)d_in[3];
    float4* out = (float4*)d_out;

    (void)in_sizes; (void)n_in; (void)out_size;

    const int smem = NR * sizeof(float4)                 // refs      128 KB
                   + QPB * BUF_CAP * sizeof(ull)         // survivors  64 KB
                   + 32 * 33 * sizeof(float)             // group minima
                   + 32 * sizeof(float)                  // tau
                   + 32 * sizeof(int);                   // cursors
    cudaFuncSetAttribute(knn_kernel, cudaFuncAttributeMaxDynamicSharedMemorySize, smem);

    knn_kernel<<<KNN_BLOCKS, THREADS, smem>>>(xyz_prev, xyz_cur);
    gather_kernel<<<NQ, dim3(64, 4)>>>(feat_prev, feat_cur, out);
}

// round 14
// speedup vs baseline: 1.6545x; 1.6545x over previous
#include <cuda_runtime.h>

#define NR    8192
#define NQ    4096
#define KNN_K 16
#define C4    64            // 256 channels / 4 (float4)

#define WPB          28
#define THREADS      (WPB * 32)              // 896
#define KNN_BLOCKS   ((NQ + WPB - 1) / WPB)  // 147
#define SAMPLE_ITERS 64                      // 2048 samples (refs 0..2047, raw order)
#define BUF_CAP      256
#define SLACK        1e-3f                   // >> all rounding gaps in play (~1e-5)

#define CD     32                            // cells per dim (x, y)
#define C2     (CD * CD)                     // 1024
#define GLO    (-4.0f)
#define INV_CW (4.0f)                        // cell width 0.25 over [-4, 4]

typedef unsigned long long ull;

__device__ int g_knn_idx[NQ * KNN_K];

// q2/r2: jnp.sum(x*x) = sequential add of rn squares (no FMA).
__device__ __forceinline__ float sq3(float x, float y, float z) {
    return __fadd_rn(__fadd_rn(__fmul_rn(x, x), __fmul_rn(y, y)), __fmul_rn(z, z));
}
// cross: XLA dot accumulation = fmuladd chain (seed = rn product).
__device__ __forceinline__ float dot3_fma(float ax, float ay, float az,
                                          float bx, float by, float bz) {
    return __fmaf_rn(az, bz, __fmaf_rn(ay, by, __fmul_rn(ax, bx)));
}
// Lexicographic (dist, idx) as one sortable u64 (survivor buffer only).
__device__ __forceinline__ ull make_key(float d, int r) {
    unsigned b = __float_as_uint(d);
    b ^= ((unsigned)((int)b >> 31)) | 0x80000000u;
    return ((ull)b << 32) | (unsigned)r;
}
// Monotone, clamped cell index (same function for binning and range bounds).
__device__ __forceinline__ int cell_of(float v) {
    int c = (int)floorf((v - GLO) * INV_CW);
    return min(CD - 1, max(0, c));
}

// Float-only bitonic sort of 32 lane values; returns 16th smallest (all lanes).
__device__ __forceinline__ float warp_16th(float sd, int lane) {
#pragma unroll
    for (int kk = 2; kk <= 32; kk <<= 1) {
#pragma unroll
        for (int j = kk >> 1; j > 0; j >>= 1) {
            const float o = __shfl_xor_sync(0xffffffffu, sd, j);
            const bool keepMin = (((lane & j) == 0) == ((lane & kk) == 0));
            sd = keepMin ? fminf(sd, o) : fmaxf(sd, o);
        }
    }
    return __shfl_sync(0xffffffffu, sd, KNN_K - 1);
}

// One warp per query. In-block (x,y) counting sort of refs -> phase 2 scans
// only cell rows intersecting the tau-ball rectangle (~6x fewer candidates).
__global__ void __launch_bounds__(THREADS, 1) knn_kernel(
        const float* __restrict__ xyz_prev,
        const float* __restrict__ xyz_cur) {
    extern __shared__ unsigned char smraw[];
    float4* sref   = (float4*)smraw;                                   // 128 KB
    ull*    bufs   = (ull*)(smraw + NR * sizeof(float4));              // 56 KB
    int*    cstart = (int*)(smraw + NR * sizeof(float4) + WPB * BUF_CAP * sizeof(ull));
    int*    ccur   = cstart + C2 + 1;                                  // [C2]

    const int tid  = threadIdx.x;
    const int warp = tid >> 5;
    const int lane = tid & 31;

    // 1. stage refs in RAW (random) order with r2, zero counters
    for (int i = tid; i < NR; i += THREADS) {
        const float x = xyz_prev[3 * i + 0];
        const float y = xyz_prev[3 * i + 1];
        const float z = xyz_prev[3 * i + 2];
        sref[i] = make_float4(x, y, z, sq3(x, y, z));
    }
    for (int i = tid; i < C2; i += THREADS) ccur[i] = 0;
    __syncthreads();

    // 2. histogram (x, y) cells
    for (int r = tid; r < NR; r += THREADS) {
        const float4 p = sref[r];
        atomicAdd(&ccur[cell_of(p.y) * CD + cell_of(p.x)], 1);
    }
    __syncthreads();

    // 3a. warp 0: exclusive prefix over 1024 cells (lane owns 32 cells)
    if (warp == 0) {
        const int c0 = lane * 32;
        int s = 0;
#pragma unroll
        for (int k = 0; k < 32; ++k) s += ccur[c0 + k];
        int excl = s;
#pragma unroll
        for (int off = 1; off < 32; off <<= 1) {
            const int v = __shfl_up_sync(0xffffffffu, excl, off);
            if (lane >= off) excl += v;
        }
        excl -= s;
        int run = excl;
#pragma unroll
        for (int k = 0; k < 32; ++k) {
            const int c = ccur[c0 + k];
            cstart[c0 + k] = run;
            ccur[c0 + k] = run;          // scatter cursor
            run += c;
        }
        if (lane == 31) cstart[C2] = NR;
    }

    // 3b. all warps: phase-1 tau from raw sref[0..2048) (concurrent w/ prefix)
    const int q = blockIdx.x * WPB + warp;
    const bool active = (q < NQ);
    float qx = 0, qy = 0, qz = 0, q2 = 0, R2 = 0, Rr = 0;
    if (active) {
        qx = xyz_cur[3 * q + 0];
        qy = xyz_cur[3 * q + 1];
        qz = xyz_cur[3 * q + 2];
        q2 = sq3(qx, qy, qz);

        const float INF = __int_as_float(0x7f800000);
        float m0 = INF, m1 = INF, m2 = INF, m3 = INF;
        for (int i = 0; i < SAMPLE_ITERS; i += 4) {
            const float4 p0 = sref[lane + 32 * (i + 0)];
            const float4 p1 = sref[lane + 32 * (i + 1)];
            const float4 p2 = sref[lane + 32 * (i + 2)];
            const float4 p3 = sref[lane + 32 * (i + 3)];
            m0 = fminf(m0, __fmaf_rn(-2.0f, dot3_fma(qx, qy, qz, p0.x, p0.y, p0.z), p0.w));
            m1 = fminf(m1, __fmaf_rn(-2.0f, dot3_fma(qx, qy, qz, p1.x, p1.y, p1.z), p1.w));
            m2 = fminf(m2, __fmaf_rn(-2.0f, dot3_fma(qx, qy, qz, p2.x, p2.y, p2.z), p2.w));
            m3 = fminf(m3, __fmaf_rn(-2.0f, dot3_fma(qx, qy, qz, p3.x, p3.y, p3.z), p3.w));
        }
        const float tau_t = warp_16th(fminf(fminf(m0, m1), fminf(m2, m3)), lane);
        // d-space superset threshold (>= true d16) + slack for rounding gaps
        R2 = fmaxf(tau_t + q2 + SLACK, 0.0f) + SLACK;
        Rr = sqrtf(R2) + 1e-3f;
    }
    __syncthreads();

    // 4. scatter refs cell-sorted (re-read gmem; raw sref is dead now)
    for (int r = tid; r < NR; r += THREADS) {
        const float x = xyz_prev[3 * r + 0];
        const float y = xyz_prev[3 * r + 1];
        const float z = xyz_prev[3 * r + 2];
        const int pos = atomicAdd(&ccur[cell_of(y) * CD + cell_of(x)], 1);
        sref[pos] = make_float4(x, y, z, __int_as_float(r));
    }
    __syncthreads();
    if (!active) return;                 // after last block-wide sync

    ull* wbuf = bufs + warp * BUF_CAP;

    // 5. phase-2: scan cell rows of the rectangle, ballot-compact survivors
    const int cxlo = cell_of(qx - Rr), cxhi = cell_of(qx + Rr);
    const int cylo = cell_of(qy - Rr), cyhi = cell_of(qy + Rr);
    int base = 0;
    const unsigned lt_mask = (1u << lane) - 1u;
    for (int cy = cylo; cy <= cyhi; ++cy) {
        const int s = cstart[cy * CD + cxlo];
        const int e = cstart[cy * CD + cxhi + 1];
        for (int b = s; b < e; b += 32) {
            const int i = b + lane;
            const bool valid = (i < e);
            const float4 p = sref[valid ? i : s];
            const float r2 = sq3(p.x, p.y, p.z);
            const float cr = dot3_fma(qx, qy, qz, p.x, p.y, p.z);
            const float d  = __fmaf_rn(-2.0f, cr, __fadd_rn(q2, r2));
            const bool pred = valid && (d <= R2);
            const unsigned m = __ballot_sync(0xffffffffu, pred);
            if (pred) {
                const int pos = base + __popc(m & lt_mask);
                if (pos < BUF_CAP) wbuf[pos] = make_key(d, __float_as_int(p.w));
            }
            base += __popc(m);
        }
    }
    const int cnt = (base < BUF_CAP) ? base : BUF_CAP;   // >= 16 guaranteed
    __syncwarp();

    // 6. exact selection: 16 argmin-extract rounds (total-order keys)
    for (int sel = 0; sel < KNN_K; ++sel) {
        ull best = ~0ull;
        int bpos = -1;
        for (int i = lane; i < cnt; i += 32) {
            const ull v = wbuf[i];
            if (v < best) { best = v; bpos = i; }
        }
#pragma unroll
        for (int off = 16; off > 0; off >>= 1) {
            const ull ob = __shfl_down_sync(0xffffffffu, best, off);
            const int op = __shfl_down_sync(0xffffffffu, bpos, off);
            if (ob < best) { best = ob; bpos = op; }
        }
        bpos = __shfl_sync(0xffffffffu, bpos, 0);
        if (lane == 0) g_knn_idx[q * KNN_K + sel] = (int)(wbuf[bpos] & 0xffffffffu);
        if (lane == (bpos & 31)) wbuf[bpos] = ~0ull;
        __syncwarp();
    }
}

// One block per query. blockDim = (64, 4). Thread y owns neighbors 4y..4y+3:
// one int4 idx load -> 4 independent gathers (MLP=4), cur reused from regs.
__global__ void __launch_bounds__(256) gather_kernel(
        const float4* __restrict__ feat_prev,
        const float4* __restrict__ feat_cur,
        float4* __restrict__ out) {
    const int q  = blockIdx.x;
    const int c4 = threadIdx.x;   // 0..63
    const int y  = threadIdx.y;   // 0..3

    const float4 cur = feat_cur[q * C4 + c4];
    const int4 iv = __ldg((const int4*)(g_knn_idx + q * KNN_K + 4 * y));

    const float4 p0 = feat_prev[iv.x * C4 + c4];
    const float4 p1 = feat_prev[iv.y * C4 + c4];
    const float4 p2 = feat_prev[iv.z * C4 + c4];
    const float4 p3 = feat_prev[iv.w * C4 + c4];

    const int row0 = q * KNN_K + 4 * y;
#pragma unroll
    for (int jj = 0; jj < 4; ++jj) {
        const float4 p = (jj == 0) ? p0 : (jj == 1) ? p1 : (jj == 2) ? p2 : p3;
        float4 dv;
        dv.x = p.x - cur.x; dv.y = p.y - cur.y;
        dv.z = p.z - cur.z; dv.w = p.w - cur.w;
        const long long row = row0 + jj;
        __stcs(&out[row * 128 + c4], dv);
        __stcs(&out[row * 128 + C4 + c4], cur);
    }
}

extern "C" void kernel_launch(void* const* d_in, const int* in_sizes, int n_in,
                              void* d_out, int out_size) {
    const float*  xyz_prev  = (const float*)d_in[0];
    const float*  xyz_cur   = (const float*)d_in[1];
    const float4* feat_prev = (const float4*)d_in[2];
    const float4* feat_cur  = (const float4*)d_in[3];
    float4* out = (float4*)d_out;

    (void)in_sizes; (void)n_in; (void)out_size;

    const int smem = NR * sizeof(float4)             // refs        128 KB
                   + WPB * BUF_CAP * sizeof(ull)     // survivors    56 KB
                   + (C2 + 1 + C2) * sizeof(int);    // starts+cursors ~8 KB
    cudaFuncSetAttribute(knn_kernel, cudaFuncAttributeMaxDynamicSharedMemorySize, smem);

    knn_kernel<<<KNN_BLOCKS, THREADS, smem>>>(xyz_prev, xyz_cur);
    gather_kernel<<<NQ, dim3(64, 4)>>>(feat_prev, feat_cur, out);
}